// round 13
// baseline (speedup 1.0000x reference)
#include <cuda_runtime.h>
#include <cstdint>

#define BATCH 32
#define NN 100
#define HH 32
#define DD 3200
#define NF 16
#define NSPLIT 100
#define ILEN (DD/NSPLIT)     // 32
#define CI 4
#define NCHUNK (ILEN/CI)     // 8
#define TO 128               // 64 o-lanes x 2 batch-halves; 2 outputs/thread
#define NW 1596
#define GPARTS 5

// ---- scratch (device globals: allocation-free) ----
__device__ float g_hs[BATCH*DD];
__device__ float g_gpart[BATCH][GPARTS][3];
__device__ float g_feat[(size_t)DD*NF*BATCH];          // [i][f][b]  6.55 MB

// ===================== stage 0: graph conv + layernorm -> hs (alpha + out-zero fused)
__global__ void k_gconv(const float* __restrict__ inputs,
                        const float* __restrict__ hidden,
                        const float* __restrict__ lap,
                        const float* __restrict__ corr,
                        const float* __restrict__ gc_w,
                        const float* __restrict__ gc_b,
                        const float* __restrict__ ln_g,
                        const float* __restrict__ ln_b,
                        float* __restrict__ outz) {
    int blk = blockIdx.x;            // b*100 + m
    int b = blk / NN;
    int m = blk % NN;
    int o = threadIdx.x;             // 0..31, one warp

    // zero the atomic-epilogue target: 3200 blocks x 32 threads == BATCH*DD
    outz[blk*32 + o] = 0.f;

    __shared__ float salpha[NN];
    for (int n = o; n < NN; n += 32) {
        float s = 0.f;
        #pragma unroll 4
        for (int bb = 0; bb < BATCH; ++bb) s += inputs[bb*NN + n];
        s *= (1.f/BATCH);
        salpha[n] = 1.f / (1.f + expf(-s));
    }
    __syncwarp();

    float axh = 0.f, ax0 = 0.f;
    for (int n = 0; n < NN; ++n) {
        float al = salpha[n];
        float a  = al * lap[m*NN + n] + (1.f - al) * corr[m*NN + n];
        ax0 += a * inputs[b*NN + n];
        axh += a * hidden[(size_t)(b*NN + n)*HH + o];
    }
    __shared__ float sax[HH];
    sax[o] = axh;
    __syncwarp();

    float h = gc_b[o] + ax0 * gc_w[o];
    #pragma unroll
    for (int f = 0; f < HH; ++f)
        h += sax[f] * gc_w[(f+1)*HH + o];

    float mu = h;
    #pragma unroll
    for (int off = 16; off; off >>= 1) mu += __shfl_xor_sync(0xffffffffu, mu, off);
    mu *= (1.f/HH);
    float dv = h - mu;
    float v = dv*dv;
    #pragma unroll
    for (int off = 16; off; off >>= 1) v += __shfl_xor_sync(0xffffffffu, v, off);
    v *= (1.f/HH);
    float out = dv * rsqrtf(v + 1e-5f) * ln_g[o] + ln_b[o];
    g_hs[(size_t)blk*HH + o] = out;
}

// ===================== stage 1: gating partials =====================
__global__ void k_gates_part() {
    int part = blockIdx.x;
    int b    = blockIdx.y;
    int tid  = threadIdx.x;
    __shared__ float sh[DD];
    __shared__ float ct[10], st[10];
    __shared__ float red[3][256];

    if (tid < 10) { ct[tid] = cospif(0.2f * tid); st[tid] = sinpif(0.2f * tid); }
    for (int i = tid; i < DD; i += 256) sh[i] = g_hs[(size_t)b*DD + i];
    __syncthreads();

    float ps = 0.f, ss = 0.f, ns = 0.f;
    for (int w = part + GPARTS*tid; w < NW; w += GPARTS*256) {
        int s0 = 2*w;
        float x[10];
        #pragma unroll
        for (int j = 0; j < 10; ++j) x[j] = sh[s0 + j];
        #pragma unroll
        for (int k = 0; k < 10; ++k) {
            float re = 0.f, im = 0.f;
            #pragma unroll
            for (int j = 0; j < 10; ++j) {
                int t = (j*k) % 10;
                re += x[j] * ct[t];
                im += x[j] * st[t];
            }
            ps += sqrtf(re*re + im*im);
        }
        #pragma unroll
        for (int j = 0; j < 9; ++j) ss += fabsf(x[j+1] - x[j]);
    }
    for (int i = part + GPARTS*tid; i < DD-2; i += GPARTS*256)
        ns += fabsf(sh[i+2] - 2.f*sh[i+1] + sh[i]);

    red[0][tid] = ps; red[1][tid] = ss; red[2][tid] = ns;
    __syncthreads();
    for (int off = 128; off; off >>= 1) {
        if (tid < off) {
            red[0][tid] += red[0][tid+off];
            red[1][tid] += red[1][tid+off];
            red[2][tid] += red[2][tid+off];
        }
        __syncthreads();
    }
    if (tid == 0) {
        g_gpart[b][part][0] = red[0][0];
        g_gpart[b][part][1] = red[1][0];
        g_gpart[b][part][2] = red[2][0];
    }
}

// ===================== stage 2: gates finalize + feature tensor ========
__global__ void k_featgates(const float* __restrict__ mnp, const float* __restrict__ mxp,
                            const float* __restrict__ mns, const float* __restrict__ mxs,
                            const float* __restrict__ mnn, const float* __restrict__ mxn) {
    __shared__ float sg[BATCH][3];
    int tid = threadIdx.x;
    if (tid < BATCH) {
        int b = tid;
        float psum = 0.f, ssum = 0.f, nsum = 0.f;
        #pragma unroll
        for (int k = 0; k < GPARTS; ++k) {
            psum += g_gpart[b][k][0];
            ssum += g_gpart[b][k][1];
            nsum += g_gpart[b][k][2];
        }
        float pstat = psum / (float)(NW*10);
        float sstat = ssum / (float)(NW*9);
        float nstat = nsum / (float)(DD-2);
        float p  = fabsf((pstat - *mnp) / (*mxp - *mnp + 1e-8f));
        float s  = 1.f - fabsf((sstat - *mns) / (*mxs - *mns + 1e-8f));
        float nv = fabsf((nstat - *mnn) / (*mxn - *mnn + 1e-8f));
        float a0 = fabsf(p), a1 = fabsf(s), a2 = fabsf(nv);
        float mm = fmaxf(a0, fmaxf(a1, a2));
        float e0 = expf(a0-mm), e1 = expf(a1-mm), e2 = expf(a2-mm);
        float inv = 1.f / (e0 + e1 + e2);
        sg[b][0] = e0*inv; sg[b][1] = e1*inv; sg[b][2] = e2*inv;
    }
    __syncthreads();

    int idx = blockIdx.x*blockDim.x + tid;
    if (idx >= BATCH*DD) return;
    int b = idx & 31;
    int i = idx >> 5;
    float x  = g_hs[(size_t)b*DD + i];
    float g0 = sg[b][0], g1 = sg[b][1], g2 = sg[b][2];
    float* fo = g_feat + (size_t)i*(NF*BATCH) + b;

    // Chebyshev: cos(d*arccos(tanh(.))) == T_d(tanh(.))
    float t  = tanhf(g0*x);
    float t2 = 2.f*t*t - 1.f;
    float t3 = 2.f*t*t2 - t;
    fo[0*BATCH] = 1.f; fo[1*BATCH] = t; fo[2*BATCH] = t2; fo[3*BATCH] = t3;

    // SiLU + B-spline
    float xb = g1*x;
    fo[4*BATCH] = xb / (1.f + expf(-xb));
    float bb[11];
    #pragma unroll
    for (int tt = 0; tt < 11; ++tt) {
        float gl = (float)(tt-3) * 0.4f - 1.f;
        float gr = (float)(tt-2) * 0.4f - 1.f;
        bb[tt] = (xb >= gl && xb < gr) ? 1.f : 0.f;
    }
    #pragma unroll
    for (int d = 1; d <= 3; ++d) {
        float inv = 1.f / (0.4f * (float)d);
        #pragma unroll
        for (int tt = 0; tt < 10; ++tt) {
            if (tt < 11 - d) {
                float gl = (float)(tt-3) * 0.4f - 1.f;
                float gr = (float)(tt+d+1-3) * 0.4f - 1.f;
                bb[tt] = (xb - gl)*inv*bb[tt] + (gr - xb)*inv*bb[tt+1];
            }
        }
    }
    #pragma unroll
    for (int k = 0; k < 8; ++k) fo[(5+k)*BATCH] = bb[k];

    // Taylor powers
    float xt = g2*x;
    fo[13*BATCH] = xt;
    fo[14*BATCH] = xt*xt;
    fo[15*BATCH] = xt*xt*xt;
}

// ===================== stage 3: fused contraction (2 out x 16 batches / thread) ====
__device__ __forceinline__ void cpa16(void* s, const void* g) {
    unsigned ss = (unsigned)__cvta_generic_to_shared(s);
    asm volatile("cp.async.cg.shared.global [%0], [%1], 16;" :: "r"(ss), "l"(g));
}
__device__ __forceinline__ unsigned long long dup2(float w) {
    unsigned long long r;
    asm("mov.b64 %0, {%1, %1};" : "=l"(r) : "f"(w));
    return r;
}

__global__ void __launch_bounds__(TO, 5) k_gemm(const float* __restrict__ cheb,
                                                const float* __restrict__ basew,
                                                const float* __restrict__ spline,
                                                const float* __restrict__ taylor,
                                                float* __restrict__ out) {
    int tid = threadIdx.x;
    int bh  = tid & 1;                // batch half: 0 -> b[0:16), 1 -> b[16:32)
    int oo  = tid >> 1;               // 0..63
    int o0  = blockIdx.x*128 + oo;    // blockIdx.x in [0,25)
    int o1  = o0 + 64;
    int sp  = blockIdx.y;
    int i0  = sp * ILEN;

    __shared__ __align__(16) float sf[2][CI*NF*BATCH];   // features, 2 x 8 KB
    __shared__ __align__(16) float ssp[CI][2][128][4];   // spline tile, 16 KB (single buf)

    unsigned long long acc0[8], acc1[8];
    #pragma unroll
    for (int p = 0; p < 8; ++p) { acc0[p] = 0ull; acc1[p] = 0ull; }

    int oBase = blockIdx.x*128;

    // ---- spline tile staging: lanes traverse K -> fully packed lines ----
    // flat = r*128 + tid; o = flat>>3 (block-local), q = flat&7; ii=q>>1, fh=q&1
    #define STAGE_SPL(cc) do {                                                          \
        int ib_ = i0 + (cc)*CI;                                                         \
        _Pragma("unroll")                                                               \
        for (int r = 0; r < 8; ++r) {                                                   \
            int flat = r*128 + tid;                                                     \
            int ol = flat >> 3;                                                         \
            int q  = flat & 7;                                                          \
            int iiq = q >> 1, fhq = q & 1;                                              \
            cpa16(&ssp[iiq][fhq][ol][0],                                                \
                  spline + (size_t)(oBase + ol)*(DD*8) + (size_t)(ib_ + iiq)*8 + fhq*4);\
        }                                                                               \
        asm volatile("cp.async.commit_group;");                                         \
    } while (0)

    #define STAGE_FEAT(cc, buf) do {                                                   \
        const float4* src_ = (const float4*)(g_feat + (size_t)(i0 + (cc)*CI)*(NF*BATCH));\
        float4* dst_ = (float4*)sf[buf];                                                \
        _Pragma("unroll")                                                               \
        for (int r = 0; r < 4; ++r)                                                     \
            cpa16(&dst_[tid + r*TO], &src_[tid + r*TO]);                                \
        asm volatile("cp.async.commit_group;");                                         \
    } while (0)

    // prologue: feat(0), spline(0)
    STAGE_FEAT(0, 0);
    STAGE_SPL(0);

    for (int c = 0; c < NCHUNK; ++c) {
        if (c + 1 < NCHUNK) {
            STAGE_FEAT(c + 1, (c+1)&1);
            asm volatile("cp.async.wait_group 1;");  // completes feat(c)+spline(c)
        } else {
            asm volatile("cp.async.wait_group 0;");
        }
        __syncthreads();

        const float* sb = sf[c&1];
        int ibase = i0 + c*CI;

        // basew for this chunk (contiguous in i): 1 float4 per o
        float bw0[4], bw1[4];
        {
            float4 a = *(const float4*)(basew + (size_t)o0*DD + ibase);
            bw0[0]=a.x; bw0[1]=a.y; bw0[2]=a.z; bw0[3]=a.w;
            float4 b = *(const float4*)(basew + (size_t)o1*DD + ibase);
            bw1[0]=b.x; bw1[1]=b.y; bw1[2]=b.z; bw1[3]=b.w;
        }

        #pragma unroll
        for (int ii = 0; ii < CI; ++ii) {
            int i = ibase + ii;
            float wv0[16], wv1[16];

            // cheb f0..3 (i-major LDG)
            {
                float4 cw = *(const float4*)(cheb + (size_t)i*(DD*4) + (size_t)o0*4);
                wv0[0]=cw.x; wv0[1]=cw.y; wv0[2]=cw.z; wv0[3]=cw.w;
                float4 cx = *(const float4*)(cheb + (size_t)i*(DD*4) + (size_t)o1*4);
                wv1[0]=cx.x; wv1[1]=cx.y; wv1[2]=cx.z; wv1[3]=cx.w;
            }
            wv0[4] = bw0[ii];
            wv1[4] = bw1[ii];
            // spline f5..12 from staged smem (conflict-free LDS.128)
            {
                float4 a = *(const float4*)&ssp[ii][0][oo][0];
                float4 b = *(const float4*)&ssp[ii][1][oo][0];
                wv0[5]=a.x; wv0[6]=a.y; wv0[7]=a.z; wv0[8]=a.w;
                wv0[9]=b.x; wv0[10]=b.y; wv0[11]=b.z; wv0[12]=b.w;
                float4 c4 = *(const float4*)&ssp[ii][0][oo+64][0];
                float4 d4 = *(const float4*)&ssp[ii][1][oo+64][0];
                wv1[5]=c4.x; wv1[6]=c4.y; wv1[7]=c4.z; wv1[8]=c4.w;
                wv1[9]=d4.x; wv1[10]=d4.y; wv1[11]=d4.z; wv1[12]=d4.w;
            }
            // taylor f13..15 (i-major LDG)
            {
                const float* tp = taylor + (size_t)i*(DD*3) + (size_t)o0*3;
                wv0[13]=__ldg(tp+0); wv0[14]=__ldg(tp+1); wv0[15]=__ldg(tp+2);
                const float* tq = taylor + (size_t)i*(DD*3) + (size_t)o1*3;
                wv1[13]=__ldg(tq+0); wv1[14]=__ldg(tq+1); wv1[15]=__ldg(tq+2);
            }

            #pragma unroll
            for (int f = 0; f < 16; ++f) {
                unsigned long long wA = dup2(wv0[f]);
                unsigned long long wB = dup2(wv1[f]);
                const ulonglong2* fp = (const ulonglong2*)&sb[ii*(NF*BATCH) + f*BATCH + bh*16];
                #pragma unroll
                for (int p = 0; p < 4; ++p) {
                    ulonglong2 q = fp[p];   // one LDS.128 feeds 4 FFMA2
                    asm("fma.rn.f32x2 %0, %1, %2, %0;" : "+l"(acc0[2*p])   : "l"(q.x), "l"(wA));
                    asm("fma.rn.f32x2 %0, %1, %2, %0;" : "+l"(acc0[2*p+1]) : "l"(q.y), "l"(wA));
                    asm("fma.rn.f32x2 %0, %1, %2, %0;" : "+l"(acc1[2*p])   : "l"(q.x), "l"(wB));
                    asm("fma.rn.f32x2 %0, %1, %2, %0;" : "+l"(acc1[2*p+1]) : "l"(q.y), "l"(wB));
                }
            }
        }
        __syncthreads();               // ssp reads done -> safe to restage

        if (c + 1 < NCHUNK) STAGE_SPL(c + 1);
    }
    #undef STAGE_SPL
    #undef STAGE_FEAT

    // ---- epilogue: RED directly into d_out (out[b*DD + o]) ----
    #pragma unroll
    for (int p = 0; p < 8; ++p) {
        float2 v0 = *(float2*)&acc0[p];
        float2 v1 = *(float2*)&acc1[p];
        int b = bh*16 + 2*p;
        atomicAdd(out + (size_t)b    *DD + o0, v0.x);
        atomicAdd(out + (size_t)(b+1)*DD + o0, v0.y);
        atomicAdd(out + (size_t)b    *DD + o1, v1.x);
        atomicAdd(out + (size_t)(b+1)*DD + o1, v1.y);
    }
}

extern "C" void kernel_launch(void* const* d_in, const int* in_sizes, int n_in,
                              void* d_out, int out_size) {
    const float* inputs = (const float*)d_in[0];
    const float* hidden = (const float*)d_in[1];
    const float* lap    = (const float*)d_in[2];
    const float* corr   = (const float*)d_in[3];
    const float* gc_w   = (const float*)d_in[4];
    const float* gc_b   = (const float*)d_in[5];
    const float* ln_g   = (const float*)d_in[6];
    const float* ln_b   = (const float*)d_in[7];
    const float* cheb   = (const float*)d_in[8];
    const float* basew  = (const float*)d_in[9];
    const float* spline = (const float*)d_in[10];
    const float* taylor = (const float*)d_in[11];
    float* out = (float*)d_out;

    k_gconv<<<BATCH*NN, 32>>>(inputs, hidden, lap, corr, gc_w, gc_b, ln_g, ln_b, out);
    k_gates_part<<<dim3(GPARTS, BATCH), 256>>>();
    k_featgates<<<(BATCH*DD + 255)/256, 256>>>((const float*)d_in[12], (const float*)d_in[13],
                                               (const float*)d_in[14], (const float*)d_in[15],
                                               (const float*)d_in[16], (const float*)d_in[17]);
    k_gemm<<<dim3(DD/128, NSPLIT), TO>>>(cheb, basew, spline, taylor, out);
}

// round 14
// speedup vs baseline: 1.0506x; 1.0506x over previous
#include <cuda_runtime.h>
#include <cstdint>

#define BATCH 32
#define NN 100
#define HH 32
#define DD 3200
#define NF 16
#define NSPLIT 100
#define ILEN (DD/NSPLIT)     // 32
#define CI 4
#define NCHUNK (ILEN/CI)     // 8
#define TO 128               // 64 o-lanes x 2 batch-halves; 2 outputs/thread
#define NW 1596
#define GPARTS 5

// ---- scratch (device globals: allocation-free) ----
__device__ float g_hs[BATCH*DD];
__device__ float g_gpart[BATCH][GPARTS][3];
__device__ float g_feat[(size_t)DD*NF*BATCH];          // [i][f][b]  6.55 MB

// ===================== stage 0: graph conv + layernorm -> hs (alpha + out-zero fused)
__global__ void k_gconv(const float* __restrict__ inputs,
                        const float* __restrict__ hidden,
                        const float* __restrict__ lap,
                        const float* __restrict__ corr,
                        const float* __restrict__ gc_w,
                        const float* __restrict__ gc_b,
                        const float* __restrict__ ln_g,
                        const float* __restrict__ ln_b,
                        float* __restrict__ outz) {
    int blk = blockIdx.x;            // b*100 + m
    int b = blk / NN;
    int m = blk % NN;
    int o = threadIdx.x;             // 0..31, one warp

    // zero the atomic-epilogue target: 3200 blocks x 32 threads == BATCH*DD
    outz[blk*32 + o] = 0.f;

    __shared__ float salpha[NN];
    for (int n = o; n < NN; n += 32) {
        float s = 0.f;
        #pragma unroll 4
        for (int bb = 0; bb < BATCH; ++bb) s += inputs[bb*NN + n];
        s *= (1.f/BATCH);
        salpha[n] = 1.f / (1.f + expf(-s));
    }
    __syncwarp();

    float axh = 0.f, ax0 = 0.f;
    for (int n = 0; n < NN; ++n) {
        float al = salpha[n];
        float a  = al * lap[m*NN + n] + (1.f - al) * corr[m*NN + n];
        ax0 += a * inputs[b*NN + n];
        axh += a * hidden[(size_t)(b*NN + n)*HH + o];
    }
    __shared__ float sax[HH];
    sax[o] = axh;
    __syncwarp();

    float h = gc_b[o] + ax0 * gc_w[o];
    #pragma unroll
    for (int f = 0; f < HH; ++f)
        h += sax[f] * gc_w[(f+1)*HH + o];

    float mu = h;
    #pragma unroll
    for (int off = 16; off; off >>= 1) mu += __shfl_xor_sync(0xffffffffu, mu, off);
    mu *= (1.f/HH);
    float dv = h - mu;
    float v = dv*dv;
    #pragma unroll
    for (int off = 16; off; off >>= 1) v += __shfl_xor_sync(0xffffffffu, v, off);
    v *= (1.f/HH);
    float out = dv * rsqrtf(v + 1e-5f) * ln_g[o] + ln_b[o];
    g_hs[(size_t)blk*HH + o] = out;
}

// ===================== stage 1: gating partials =====================
__global__ void k_gates_part() {
    int part = blockIdx.x;
    int b    = blockIdx.y;
    int tid  = threadIdx.x;
    __shared__ float sh[DD];
    __shared__ float ct[10], st[10];
    __shared__ float red[3][256];

    if (tid < 10) { ct[tid] = cospif(0.2f * tid); st[tid] = sinpif(0.2f * tid); }
    for (int i = tid; i < DD; i += 256) sh[i] = g_hs[(size_t)b*DD + i];
    __syncthreads();

    float ps = 0.f, ss = 0.f, ns = 0.f;
    for (int w = part + GPARTS*tid; w < NW; w += GPARTS*256) {
        int s0 = 2*w;
        float x[10];
        #pragma unroll
        for (int j = 0; j < 10; ++j) x[j] = sh[s0 + j];
        #pragma unroll
        for (int k = 0; k < 10; ++k) {
            float re = 0.f, im = 0.f;
            #pragma unroll
            for (int j = 0; j < 10; ++j) {
                int t = (j*k) % 10;
                re += x[j] * ct[t];
                im += x[j] * st[t];
            }
            ps += sqrtf(re*re + im*im);
        }
        #pragma unroll
        for (int j = 0; j < 9; ++j) ss += fabsf(x[j+1] - x[j]);
    }
    for (int i = part + GPARTS*tid; i < DD-2; i += GPARTS*256)
        ns += fabsf(sh[i+2] - 2.f*sh[i+1] + sh[i]);

    red[0][tid] = ps; red[1][tid] = ss; red[2][tid] = ns;
    __syncthreads();
    for (int off = 128; off; off >>= 1) {
        if (tid < off) {
            red[0][tid] += red[0][tid+off];
            red[1][tid] += red[1][tid+off];
            red[2][tid] += red[2][tid+off];
        }
        __syncthreads();
    }
    if (tid == 0) {
        g_gpart[b][part][0] = red[0][0];
        g_gpart[b][part][1] = red[1][0];
        g_gpart[b][part][2] = red[2][0];
    }
}

// ===================== stage 2: gates finalize + feature tensor ========
__global__ void k_featgates(const float* __restrict__ mnp, const float* __restrict__ mxp,
                            const float* __restrict__ mns, const float* __restrict__ mxs,
                            const float* __restrict__ mnn, const float* __restrict__ mxn) {
    __shared__ float sg[BATCH][3];
    int tid = threadIdx.x;
    if (tid < BATCH) {
        int b = tid;
        float psum = 0.f, ssum = 0.f, nsum = 0.f;
        #pragma unroll
        for (int k = 0; k < GPARTS; ++k) {
            psum += g_gpart[b][k][0];
            ssum += g_gpart[b][k][1];
            nsum += g_gpart[b][k][2];
        }
        float pstat = psum / (float)(NW*10);
        float sstat = ssum / (float)(NW*9);
        float nstat = nsum / (float)(DD-2);
        float p  = fabsf((pstat - *mnp) / (*mxp - *mnp + 1e-8f));
        float s  = 1.f - fabsf((sstat - *mns) / (*mxs - *mns + 1e-8f));
        float nv = fabsf((nstat - *mnn) / (*mxn - *mnn + 1e-8f));
        float a0 = fabsf(p), a1 = fabsf(s), a2 = fabsf(nv);
        float mm = fmaxf(a0, fmaxf(a1, a2));
        float e0 = expf(a0-mm), e1 = expf(a1-mm), e2 = expf(a2-mm);
        float inv = 1.f / (e0 + e1 + e2);
        sg[b][0] = e0*inv; sg[b][1] = e1*inv; sg[b][2] = e2*inv;
    }
    __syncthreads();

    int idx = blockIdx.x*blockDim.x + tid;
    if (idx >= BATCH*DD) return;
    int b = idx & 31;
    int i = idx >> 5;
    float x  = g_hs[(size_t)b*DD + i];
    float g0 = sg[b][0], g1 = sg[b][1], g2 = sg[b][2];
    float* fo = g_feat + (size_t)i*(NF*BATCH) + b;

    // Chebyshev: cos(d*arccos(tanh(.))) == T_d(tanh(.))
    float t  = tanhf(g0*x);
    float t2 = 2.f*t*t - 1.f;
    float t3 = 2.f*t*t2 - t;
    fo[0*BATCH] = 1.f; fo[1*BATCH] = t; fo[2*BATCH] = t2; fo[3*BATCH] = t3;

    // SiLU + B-spline
    float xb = g1*x;
    fo[4*BATCH] = xb / (1.f + expf(-xb));
    float bb[11];
    #pragma unroll
    for (int tt = 0; tt < 11; ++tt) {
        float gl = (float)(tt-3) * 0.4f - 1.f;
        float gr = (float)(tt-2) * 0.4f - 1.f;
        bb[tt] = (xb >= gl && xb < gr) ? 1.f : 0.f;
    }
    #pragma unroll
    for (int d = 1; d <= 3; ++d) {
        float inv = 1.f / (0.4f * (float)d);
        #pragma unroll
        for (int tt = 0; tt < 10; ++tt) {
            if (tt < 11 - d) {
                float gl = (float)(tt-3) * 0.4f - 1.f;
                float gr = (float)(tt+d+1-3) * 0.4f - 1.f;
                bb[tt] = (xb - gl)*inv*bb[tt] + (gr - xb)*inv*bb[tt+1];
            }
        }
    }
    #pragma unroll
    for (int k = 0; k < 8; ++k) fo[(5+k)*BATCH] = bb[k];

    // Taylor powers
    float xt = g2*x;
    fo[13*BATCH] = xt;
    fo[14*BATCH] = xt*xt;
    fo[15*BATCH] = xt*xt*xt;
}

// ===================== stage 3: fused contraction (2 out x 16 batches / thread) ====
__device__ __forceinline__ void cpa16(void* s, const void* g) {
    unsigned ss = (unsigned)__cvta_generic_to_shared(s);
    asm volatile("cp.async.cg.shared.global [%0], [%1], 16;" :: "r"(ss), "l"(g));
}
__device__ __forceinline__ unsigned long long dup2(float w) {
    unsigned long long r;
    asm("mov.b64 %0, {%1, %1};" : "=l"(r) : "f"(w));
    return r;
}
#define FMA2(a, q, w) asm("fma.rn.f32x2 %0, %1, %2, %0;" : "+l"(a) : "l"(q), "l"(w))

// one feature row f against 2 output weights: 4 LDS.128 -> 16 FFMA2
__device__ __forceinline__ void fmarow(const float* sb, int f, int bh,
                                       float w0, float w1,
                                       unsigned long long acc0[8],
                                       unsigned long long acc1[8]) {
    unsigned long long wA = dup2(w0);
    unsigned long long wB = dup2(w1);
    const ulonglong2* fp = (const ulonglong2*)(sb + f*BATCH + bh*16);
    #pragma unroll
    for (int p = 0; p < 4; ++p) {
        ulonglong2 q = fp[p];
        FMA2(acc0[2*p],   q.x, wA);
        FMA2(acc0[2*p+1], q.y, wA);
        FMA2(acc1[2*p],   q.x, wB);
        FMA2(acc1[2*p+1], q.y, wB);
    }
}

__global__ void __launch_bounds__(TO, 6) k_gemm(const float* __restrict__ cheb,
                                                const float* __restrict__ basew,
                                                const float* __restrict__ spline,
                                                const float* __restrict__ taylor,
                                                float* __restrict__ out) {
    int tid = threadIdx.x;
    int bh  = tid & 1;                // batch half: 0 -> b[0:16), 1 -> b[16:32)
    int oo  = tid >> 1;               // 0..63
    int o0  = blockIdx.x*128 + oo;    // blockIdx.x in [0,25)
    int o1  = o0 + 64;
    int sp  = blockIdx.y;
    int i0  = sp * ILEN;

    __shared__ __align__(16) float sf[2][CI*NF*BATCH];  // 2 x 8 KB
    unsigned long long acc0[8], acc1[8];                 // 16 batches (this half) per output
    #pragma unroll
    for (int p = 0; p < 8; ++p) { acc0[p] = 0ull; acc1[p] = 0ull; }

    // prologue: stage chunk 0 (128 threads x 4 float4 = 8 KB)
    {
        const float4* src = (const float4*)(g_feat + (size_t)i0*(NF*BATCH));
        #pragma unroll
        for (int r = 0; r < 4; ++r)
            cpa16(&((float4*)sf[0])[tid + r*TO], &src[tid + r*TO]);
        asm volatile("cp.async.commit_group;");
    }

    for (int c = 0; c < NCHUNK; ++c) {
        if (c + 1 < NCHUNK) {
            const float4* src = (const float4*)(g_feat + (size_t)(i0 + (c+1)*CI)*(NF*BATCH));
            float4* dst = (float4*)sf[(c+1)&1];
            #pragma unroll
            for (int r = 0; r < 4; ++r)
                cpa16(&dst[tid + r*TO], &src[tid + r*TO]);
            asm volatile("cp.async.commit_group;");
            asm volatile("cp.async.wait_group 1;");
        } else {
            asm volatile("cp.async.wait_group 0;");
        }
        __syncthreads();

        const float* sbase = sf[c&1];
        int ibase = i0 + c*CI;

        // basew for this chunk (contiguous in i): 1 float4 per o
        float bw0[4], bw1[4];
        {
            float4 a = *(const float4*)(basew + (size_t)o0*DD + ibase);
            bw0[0]=a.x; bw0[1]=a.y; bw0[2]=a.z; bw0[3]=a.w;
            float4 b = *(const float4*)(basew + (size_t)o1*DD + ibase);
            bw1[0]=b.x; bw1[1]=b.y; bw1[2]=b.z; bw1[3]=b.w;
        }

        #pragma unroll
        for (int ii = 0; ii < CI; ++ii) {
            int i = ibase + ii;
            const float* sb = sbase + ii*(NF*BATCH);

            // ---- cheb f0..3: load group, consume immediately ----
            {
                float4 cw = *(const float4*)(cheb + (size_t)i*(DD*4) + (size_t)o0*4);
                float4 cx = *(const float4*)(cheb + (size_t)i*(DD*4) + (size_t)o1*4);
                fmarow(sb, 0, bh, cw.x, cx.x, acc0, acc1);
                fmarow(sb, 1, bh, cw.y, cx.y, acc0, acc1);
                fmarow(sb, 2, bh, cw.z, cx.z, acc0, acc1);
                fmarow(sb, 3, bh, cw.w, cx.w, acc0, acc1);
            }
            // ---- basew f4 ----
            fmarow(sb, 4, bh, bw0[ii], bw1[ii], acc0, acc1);

            // ---- spline f5..12: two float4 groups per output, consumed in place ----
            {
                const float4* sp0 = (const float4*)(spline + (size_t)o0*(DD*8) + (size_t)i*8);
                const float4* sp1 = (const float4*)(spline + (size_t)o1*(DD*8) + (size_t)i*8);
                float4 a = sp0[0], b = sp1[0];
                fmarow(sb, 5, bh, a.x, b.x, acc0, acc1);
                fmarow(sb, 6, bh, a.y, b.y, acc0, acc1);
                fmarow(sb, 7, bh, a.z, b.z, acc0, acc1);
                fmarow(sb, 8, bh, a.w, b.w, acc0, acc1);
                float4 c4 = sp0[1], d4 = sp1[1];
                fmarow(sb, 9,  bh, c4.x, d4.x, acc0, acc1);
                fmarow(sb, 10, bh, c4.y, d4.y, acc0, acc1);
                fmarow(sb, 11, bh, c4.z, d4.z, acc0, acc1);
                fmarow(sb, 12, bh, c4.w, d4.w, acc0, acc1);
            }
            // ---- taylor f13..15 ----
            {
                const float* tp = taylor + (size_t)i*(DD*3) + (size_t)o0*3;
                const float* tq = taylor + (size_t)i*(DD*3) + (size_t)o1*3;
                float t00 = __ldg(tp+0), t01 = __ldg(tp+1), t02 = __ldg(tp+2);
                float t10 = __ldg(tq+0), t11 = __ldg(tq+1), t12 = __ldg(tq+2);
                fmarow(sb, 13, bh, t00, t10, acc0, acc1);
                fmarow(sb, 14, bh, t01, t11, acc0, acc1);
                fmarow(sb, 15, bh, t02, t12, acc0, acc1);
            }
        }
        __syncthreads();
    }

    // ---- epilogue: RED directly into d_out (out[b*DD + o]) ----
    #pragma unroll
    for (int p = 0; p < 8; ++p) {
        float2 v0 = *(float2*)&acc0[p];
        float2 v1 = *(float2*)&acc1[p];
        int b = bh*16 + 2*p;
        atomicAdd(out + (size_t)b    *DD + o0, v0.x);
        atomicAdd(out + (size_t)(b+1)*DD + o0, v0.y);
        atomicAdd(out + (size_t)b    *DD + o1, v1.x);
        atomicAdd(out + (size_t)(b+1)*DD + o1, v1.y);
    }
}

extern "C" void kernel_launch(void* const* d_in, const int* in_sizes, int n_in,
                              void* d_out, int out_size) {
    const float* inputs = (const float*)d_in[0];
    const float* hidden = (const float*)d_in[1];
    const float* lap    = (const float*)d_in[2];
    const float* corr   = (const float*)d_in[3];
    const float* gc_w   = (const float*)d_in[4];
    const float* gc_b   = (const float*)d_in[5];
    const float* ln_g   = (const float*)d_in[6];
    const float* ln_b   = (const float*)d_in[7];
    const float* cheb   = (const float*)d_in[8];
    const float* basew  = (const float*)d_in[9];
    const float* spline = (const float*)d_in[10];
    const float* taylor = (const float*)d_in[11];
    float* out = (float*)d_out;

    k_gconv<<<BATCH*NN, 32>>>(inputs, hidden, lap, corr, gc_w, gc_b, ln_g, ln_b, out);
    k_gates_part<<<dim3(GPARTS, BATCH), 256>>>();
    k_featgates<<<(BATCH*DD + 255)/256, 256>>>((const float*)d_in[12], (const float*)d_in[13],
                                               (const float*)d_in[14], (const float*)d_in[15],
                                               (const float*)d_in[16], (const float*)d_in[17]);
    k_gemm<<<dim3(DD/128, NSPLIT), TO>>>(cheb, basew, spline, taylor, out);
}

// round 16
// speedup vs baseline: 1.1200x; 1.0661x over previous
#include <cuda_runtime.h>
#include <cstdint>

#define BATCH 32
#define NN 100
#define HH 32
#define DD 3200
#define NF 16
#define NSPLIT 200
#define ILEN (DD/NSPLIT)     // 16
#define CI 4
#define NCHUNK (ILEN/CI)     // 4
#define TO 128               // 64 o-lanes x 2 batch-halves; 2 outputs/thread
#define NW 1596
#define GPARTS 5

// ---- scratch (device globals: allocation-free) ----
__device__ float g_hs[BATCH*DD];
__device__ float g_gpart[BATCH][GPARTS][3];
__device__ float g_feat[(size_t)DD*NF*BATCH];          // [i][f][b]  6.55 MB

// ===================== stage 0: graph conv + layernorm -> hs (alpha + out-zero fused)
__global__ void k_gconv(const float* __restrict__ inputs,
                        const float* __restrict__ hidden,
                        const float* __restrict__ lap,
                        const float* __restrict__ corr,
                        const float* __restrict__ gc_w,
                        const float* __restrict__ gc_b,
                        const float* __restrict__ ln_g,
                        const float* __restrict__ ln_b,
                        float* __restrict__ outz) {
    int blk = blockIdx.x;            // b*100 + m
    int b = blk / NN;
    int m = blk % NN;
    int o = threadIdx.x;             // 0..31, one warp

    // zero the atomic-epilogue target: 3200 blocks x 32 threads == BATCH*DD
    outz[blk*32 + o] = 0.f;

    __shared__ float salpha[NN];
    for (int n = o; n < NN; n += 32) {
        float s = 0.f;
        #pragma unroll 4
        for (int bb = 0; bb < BATCH; ++bb) s += inputs[bb*NN + n];
        s *= (1.f/BATCH);
        salpha[n] = 1.f / (1.f + expf(-s));
    }
    __syncwarp();

    float axh = 0.f, ax0 = 0.f;
    for (int n = 0; n < NN; ++n) {
        float al = salpha[n];
        float a  = al * lap[m*NN + n] + (1.f - al) * corr[m*NN + n];
        ax0 += a * inputs[b*NN + n];
        axh += a * hidden[(size_t)(b*NN + n)*HH + o];
    }
    __shared__ float sax[HH];
    sax[o] = axh;
    __syncwarp();

    float h = gc_b[o] + ax0 * gc_w[o];
    #pragma unroll
    for (int f = 0; f < HH; ++f)
        h += sax[f] * gc_w[(f+1)*HH + o];

    float mu = h;
    #pragma unroll
    for (int off = 16; off; off >>= 1) mu += __shfl_xor_sync(0xffffffffu, mu, off);
    mu *= (1.f/HH);
    float dv = h - mu;
    float v = dv*dv;
    #pragma unroll
    for (int off = 16; off; off >>= 1) v += __shfl_xor_sync(0xffffffffu, v, off);
    v *= (1.f/HH);
    float out = dv * rsqrtf(v + 1e-5f) * ln_g[o] + ln_b[o];
    g_hs[(size_t)blk*HH + o] = out;
}

// ===================== stage 1: gating partials =====================
__global__ void k_gates_part() {
    int part = blockIdx.x;
    int b    = blockIdx.y;
    int tid  = threadIdx.x;
    __shared__ float sh[DD];
    __shared__ float ct[10], st[10];
    __shared__ float red[3][256];

    if (tid < 10) { ct[tid] = cospif(0.2f * tid); st[tid] = sinpif(0.2f * tid); }
    for (int i = tid; i < DD; i += 256) sh[i] = g_hs[(size_t)b*DD + i];
    __syncthreads();

    float ps = 0.f, ss = 0.f, ns = 0.f;
    for (int w = part + GPARTS*tid; w < NW; w += GPARTS*256) {
        int s0 = 2*w;
        float x[10];
        #pragma unroll
        for (int j = 0; j < 10; ++j) x[j] = sh[s0 + j];
        #pragma unroll
        for (int k = 0; k < 10; ++k) {
            float re = 0.f, im = 0.f;
            #pragma unroll
            for (int j = 0; j < 10; ++j) {
                int t = (j*k) % 10;
                re += x[j] * ct[t];
                im += x[j] * st[t];
            }
            ps += sqrtf(re*re + im*im);
        }
        #pragma unroll
        for (int j = 0; j < 9; ++j) ss += fabsf(x[j+1] - x[j]);
    }
    for (int i = part + GPARTS*tid; i < DD-2; i += GPARTS*256)
        ns += fabsf(sh[i+2] - 2.f*sh[i+1] + sh[i]);

    red[0][tid] = ps; red[1][tid] = ss; red[2][tid] = ns;
    __syncthreads();
    for (int off = 128; off; off >>= 1) {
        if (tid < off) {
            red[0][tid] += red[0][tid+off];
            red[1][tid] += red[1][tid+off];
            red[2][tid] += red[2][tid+off];
        }
        __syncthreads();
    }
    if (tid == 0) {
        g_gpart[b][part][0] = red[0][0];
        g_gpart[b][part][1] = red[1][0];
        g_gpart[b][part][2] = red[2][0];
    }
}

// ===================== stage 2: gates finalize + feature tensor ========
__global__ void k_featgates(const float* __restrict__ mnp, const float* __restrict__ mxp,
                            const float* __restrict__ mns, const float* __restrict__ mxs,
                            const float* __restrict__ mnn, const float* __restrict__ mxn) {
    __shared__ float sg[BATCH][3];
    int tid = threadIdx.x;
    if (tid < BATCH) {
        int b = tid;
        float psum = 0.f, ssum = 0.f, nsum = 0.f;
        #pragma unroll
        for (int k = 0; k < GPARTS; ++k) {
            psum += g_gpart[b][k][0];
            ssum += g_gpart[b][k][1];
            nsum += g_gpart[b][k][2];
        }
        float pstat = psum / (float)(NW*10);
        float sstat = ssum / (float)(NW*9);
        float nstat = nsum / (float)(DD-2);
        float p  = fabsf((pstat - *mnp) / (*mxp - *mnp + 1e-8f));
        float s  = 1.f - fabsf((sstat - *mns) / (*mxs - *mns + 1e-8f));
        float nv = fabsf((nstat - *mnn) / (*mxn - *mnn + 1e-8f));
        float a0 = fabsf(p), a1 = fabsf(s), a2 = fabsf(nv);
        float mm = fmaxf(a0, fmaxf(a1, a2));
        float e0 = expf(a0-mm), e1 = expf(a1-mm), e2 = expf(a2-mm);
        float inv = 1.f / (e0 + e1 + e2);
        sg[b][0] = e0*inv; sg[b][1] = e1*inv; sg[b][2] = e2*inv;
    }
    __syncthreads();

    int idx = blockIdx.x*blockDim.x + tid;
    if (idx >= BATCH*DD) return;
    int b = idx & 31;
    int i = idx >> 5;
    float x  = g_hs[(size_t)b*DD + i];
    float g0 = sg[b][0], g1 = sg[b][1], g2 = sg[b][2];
    float* fo = g_feat + (size_t)i*(NF*BATCH) + b;

    // Chebyshev: cos(d*arccos(tanh(.))) == T_d(tanh(.))
    float t  = tanhf(g0*x);
    float t2 = 2.f*t*t - 1.f;
    float t3 = 2.f*t*t2 - t;
    fo[0*BATCH] = 1.f; fo[1*BATCH] = t; fo[2*BATCH] = t2; fo[3*BATCH] = t3;

    // SiLU + B-spline
    float xb = g1*x;
    fo[4*BATCH] = xb / (1.f + expf(-xb));
    float bb[11];
    #pragma unroll
    for (int tt = 0; tt < 11; ++tt) {
        float gl = (float)(tt-3) * 0.4f - 1.f;
        float gr = (float)(tt-2) * 0.4f - 1.f;
        bb[tt] = (xb >= gl && xb < gr) ? 1.f : 0.f;
    }
    #pragma unroll
    for (int d = 1; d <= 3; ++d) {
        float inv = 1.f / (0.4f * (float)d);
        #pragma unroll
        for (int tt = 0; tt < 10; ++tt) {
            if (tt < 11 - d) {
                float gl = (float)(tt-3) * 0.4f - 1.f;
                float gr = (float)(tt+d+1-3) * 0.4f - 1.f;
                bb[tt] = (xb - gl)*inv*bb[tt] + (gr - xb)*inv*bb[tt+1];
            }
        }
    }
    #pragma unroll
    for (int k = 0; k < 8; ++k) fo[(5+k)*BATCH] = bb[k];

    // Taylor powers
    float xt = g2*x;
    fo[13*BATCH] = xt;
    fo[14*BATCH] = xt*xt;
    fo[15*BATCH] = xt*xt*xt;
}

// ===================== stage 3: fused contraction (2 out x 16 batches / thread) ====
__device__ __forceinline__ void cpa16(void* s, const void* g) {
    unsigned ss = (unsigned)__cvta_generic_to_shared(s);
    asm volatile("cp.async.cg.shared.global [%0], [%1], 16;" :: "r"(ss), "l"(g));
}

__device__ __forceinline__ void loadW16(float* wv, int i, int o, float bwv,
                                        const float* __restrict__ cheb,
                                        const float* __restrict__ spline,
                                        const float* __restrict__ taylor) {
    float4 cw = *(const float4*)(cheb + (size_t)i*(DD*4) + (size_t)o*4);
    wv[0]=cw.x; wv[1]=cw.y; wv[2]=cw.z; wv[3]=cw.w;
    wv[4]=bwv;
    const float4* sp = (const float4*)(spline + (size_t)o*(DD*8) + (size_t)i*8);
    float4 s0 = sp[0], s1 = sp[1];
    wv[5]=s0.x; wv[6]=s0.y; wv[7]=s0.z; wv[8]=s0.w;
    wv[9]=s1.x; wv[10]=s1.y; wv[11]=s1.z; wv[12]=s1.w;
    const float* tp = taylor + (size_t)i*(DD*3) + (size_t)o*3;
    wv[13]=__ldg(tp+0); wv[14]=__ldg(tp+1); wv[15]=__ldg(tp+2);
}

__device__ __forceinline__ unsigned long long dup2(float w) {
    unsigned long long r;
    asm("mov.b64 %0, {%1, %1};" : "=l"(r) : "f"(w));
    return r;
}

__global__ void __launch_bounds__(TO, 5) k_gemm(const float* __restrict__ cheb,
                                                const float* __restrict__ basew,
                                                const float* __restrict__ spline,
                                                const float* __restrict__ taylor,
                                                float* __restrict__ out) {
    int tid = threadIdx.x;
    int bh  = tid & 1;                // batch half: 0 -> b[0:16), 1 -> b[16:32)
    int oo  = tid >> 1;               // 0..63
    int o0  = blockIdx.x*128 + oo;    // blockIdx.x in [0,25)
    int o1  = o0 + 64;
    int sp  = blockIdx.y;
    int i0  = sp * ILEN;

    __shared__ __align__(16) float sf[2][CI*NF*BATCH];  // 2 x 8 KB
    unsigned long long acc0[8], acc1[8];                 // 16 batches (this half) per output
    #pragma unroll
    for (int p = 0; p < 8; ++p) { acc0[p] = 0ull; acc1[p] = 0ull; }

    // prologue: stage chunk 0 (128 threads x 4 float4 = 8 KB)
    {
        const float4* src = (const float4*)(g_feat + (size_t)i0*(NF*BATCH));
        #pragma unroll
        for (int r = 0; r < 4; ++r)
            cpa16(&((float4*)sf[0])[tid + r*TO], &src[tid + r*TO]);
        asm volatile("cp.async.commit_group;");
    }

    for (int c = 0; c < NCHUNK; ++c) {
        if (c + 1 < NCHUNK) {
            const float4* src = (const float4*)(g_feat + (size_t)(i0 + (c+1)*CI)*(NF*BATCH));
            float4* dst = (float4*)sf[(c+1)&1];
            #pragma unroll
            for (int r = 0; r < 4; ++r)
                cpa16(&dst[tid + r*TO], &src[tid + r*TO]);
            asm volatile("cp.async.commit_group;");
            asm volatile("cp.async.wait_group 1;");
        } else {
            asm volatile("cp.async.wait_group 0;");
        }
        __syncthreads();

        const float* sb = sf[c&1];
        int ibase = i0 + c*CI;

        // basew for this chunk (contiguous in i): 1 float4 per o
        float bw0[4], bw1[4];
        {
            float4 a = *(const float4*)(basew + (size_t)o0*DD + ibase);
            bw0[0]=a.x; bw0[1]=a.y; bw0[2]=a.z; bw0[3]=a.w;
            float4 b = *(const float4*)(basew + (size_t)o1*DD + ibase);
            bw1[0]=b.x; bw1[1]=b.y; bw1[2]=b.z; bw1[3]=b.w;
        }

        #pragma unroll
        for (int ii = 0; ii < CI; ++ii) {
            int i = ibase + ii;
            float wv0[16], wv1[16];
            loadW16(wv0, i, o0, bw0[ii], cheb, spline, taylor);
            loadW16(wv1, i, o1, bw1[ii], cheb, spline, taylor);

            #pragma unroll
            for (int f = 0; f < 16; ++f) {
                unsigned long long wA = dup2(wv0[f]);
                unsigned long long wB = dup2(wv1[f]);
                const ulonglong2* fp = (const ulonglong2*)&sb[ii*(NF*BATCH) + f*BATCH + bh*16];
                #pragma unroll
                for (int p = 0; p < 4; ++p) {
                    ulonglong2 q = fp[p];   // one LDS.128 feeds 4 FFMA2
                    asm("fma.rn.f32x2 %0, %1, %2, %0;" : "+l"(acc0[2*p])   : "l"(q.x), "l"(wA));
                    asm("fma.rn.f32x2 %0, %1, %2, %0;" : "+l"(acc0[2*p+1]) : "l"(q.y), "l"(wA));
                    asm("fma.rn.f32x2 %0, %1, %2, %0;" : "+l"(acc1[2*p])   : "l"(q.x), "l"(wB));
                    asm("fma.rn.f32x2 %0, %1, %2, %0;" : "+l"(acc1[2*p+1]) : "l"(q.y), "l"(wB));
                }
            }
        }
        __syncthreads();
    }

    // ---- epilogue: RED directly into d_out (out[b*DD + o]) ----
    #pragma unroll
    for (int p = 0; p < 8; ++p) {
        float2 v0 = *(float2*)&acc0[p];
        float2 v1 = *(float2*)&acc1[p];
        int b = bh*16 + 2*p;
        atomicAdd(out + (size_t)b    *DD + o0, v0.x);
        atomicAdd(out + (size_t)(b+1)*DD + o0, v0.y);
        atomicAdd(out + (size_t)b    *DD + o1, v1.x);
        atomicAdd(out + (size_t)(b+1)*DD + o1, v1.y);
    }
}

extern "C" void kernel_launch(void* const* d_in, const int* in_sizes, int n_in,
                              void* d_out, int out_size) {
    const float* inputs = (const float*)d_in[0];
    const float* hidden = (const float*)d_in[1];
    const float* lap    = (const float*)d_in[2];
    const float* corr   = (const float*)d_in[3];
    const float* gc_w   = (const float*)d_in[4];
    const float* gc_b   = (const float*)d_in[5];
    const float* ln_g   = (const float*)d_in[6];
    const float* ln_b   = (const float*)d_in[7];
    const float* cheb   = (const float*)d_in[8];
    const float* basew  = (const float*)d_in[9];
    const float* spline = (const float*)d_in[10];
    const float* taylor = (const float*)d_in[11];
    float* out = (float*)d_out;

    k_gconv<<<BATCH*NN, 32>>>(inputs, hidden, lap, corr, gc_w, gc_b, ln_g, ln_b, out);
    k_gates_part<<<dim3(GPARTS, BATCH), 256>>>();
    k_featgates<<<(BATCH*DD + 255)/256, 256>>>((const float*)d_in[12], (const float*)d_in[13],
                                               (const float*)d_in[14], (const float*)d_in[15],
                                               (const float*)d_in[16], (const float*)d_in[17]);
    k_gemm<<<dim3(DD/128, NSPLIT), TO>>>(cheb, basew, spline, taylor, out);
}